// round 15
// baseline (speedup 1.0000x reference)
#include <cuda_runtime.h>
#include <cstdint>
#include <cstring>

// ---------------------------------------------------------------------------
// Problem constants
// ---------------------------------------------------------------------------
#define NB 32      // batch
#define IH 225
#define IW 225
#define C  128
#define PH 8       // pooled spatial (ceil(225/32))
#define PW 8
#define OH 7
#define OW 7
#define ITERS 10
#define CG 32      // float4 channel groups (C/4)
#define NS (OH * OW)   // 49 output spatial positions
#define MAXM 9     // max distinct corner-masks per position
#define ROWSTRIDE 7200u   // IW * CG, in float4 units (compile-time)
#define NPOOL (NB * PH * PW)   // 2048 pool blocks
#define NEPI  64               // dedicated combine blocks (z == NB)

// 1 MB scratch for the pooled tensor [NB, PH, PW, C] + tickets.
__device__ float g_pooled[NB * PH * PW * C];
__device__ unsigned int g_ticket;   // pool blocks done (release-published)
__device__ unsigned int g_done;     // combine blocks done (for reset)

struct CornerTab {
    unsigned char base[NS];            // corner cell id (oh*PW + ow)
    unsigned char nmask[NS];           // number of distinct masks
    unsigned char mask[NS][MAXM];      // bit0=c00 bit1=c01 bit2=c10 bit3=c11
    float         wgt[NS][MAXM];       // multiplicity / ITERS
};

__device__ __forceinline__ float4 max4(float4 a, float4 b) {
    a.x = fmaxf(a.x, b.x);
    a.y = fmaxf(a.y, b.y);
    a.z = fmaxf(a.z, b.z);
    a.w = fmaxf(a.w, b.w);
    return a;
}

// ---------------------------------------------------------------------------
// Fused kernel.
// z in [0, NB):  pool block for (b=z, ph, pw) — R12-measured hot loop,
//                publishes its cell with syncwarp + red.release (no MEMBAR).
// z == NB:       combine block — acquire-spins on the ticket, then runs the
//                corner-mask combine for ~25 output positions.
// ---------------------------------------------------------------------------
__global__ __launch_bounds__(256) void fused_kernel(const float* __restrict__ x,
                                                    float* __restrict__ out,
                                                    CornerTab tab) {
    const int t  = threadIdx.x;

    if (blockIdx.z < NB) {
        // ------------------------- POOL PATH -------------------------
        const int pw = blockIdx.x;
        const int ph = blockIdx.y;
        const int b  = blockIdx.z;
        const int cg = t & 31;    // float4 channel group 0..31
        const int pg = t >> 5;    // position group 0..7

        int h0 = ph * 32 - 15; if (h0 < 0) h0 = 0;
        int h1 = ph * 32 + 16; if (h1 > IH - 1) h1 = IH - 1;
        int w0 = pw * 32 - 15; if (w0 < 0) w0 = 0;
        int w1 = pw * 32 + 16; if (w1 > IW - 1) w1 = IW - 1;
        const int nw = w1 - w0 + 1;

        const float4* __restrict__ xb =
            reinterpret_cast<const float4*>(x) +
            (uint32_t)b * (uint32_t)(IH * IW * CG) + (uint32_t)(w0 * CG + cg);

        float4 m0 = make_float4(-1e30f, -1e30f, -1e30f, -1e30f);
        float4 m1 = m0;

        if (nw == 32) {
            int h = h0;
            for (; h + 1 <= h1; h += 2) {
                const uint32_t o0 = (uint32_t)h * ROWSTRIDE;
                const uint32_t o1 = o0 + ROWSTRIDE;
                #pragma unroll
                for (int k = 0; k < 4; ++k) {
                    const uint32_t off = (uint32_t)(pg + 8 * k) * (uint32_t)CG;
                    m0 = max4(m0, __ldg(xb + o0 + off));
                    m1 = max4(m1, __ldg(xb + o1 + off));
                }
            }
            if (h <= h1) {
                const uint32_t o0 = (uint32_t)h * ROWSTRIDE;
                #pragma unroll
                for (int k = 0; k < 4; ++k)
                    m0 = max4(m0, __ldg(xb + o0 + (uint32_t)(pg + 8 * k) * (uint32_t)CG));
            }
        } else {
            int h = h0;
            for (; h + 1 <= h1; h += 2) {
                const uint32_t o0 = (uint32_t)h * ROWSTRIDE;
                const uint32_t o1 = o0 + ROWSTRIDE;
                #pragma unroll
                for (int k = 0; k < 5; ++k) {
                    const int w = pg + 8 * k;
                    if (w < nw) {
                        const uint32_t off = (uint32_t)w * (uint32_t)CG;
                        m0 = max4(m0, __ldg(xb + o0 + off));
                        m1 = max4(m1, __ldg(xb + o1 + off));
                    }
                }
            }
            if (h <= h1) {
                const uint32_t o0 = (uint32_t)h * ROWSTRIDE;
                #pragma unroll
                for (int k = 0; k < 5; ++k) {
                    const int w = pg + 8 * k;
                    if (w < nw) m0 = max4(m0, __ldg(xb + o0 + (uint32_t)w * (uint32_t)CG));
                }
            }
        }
        m0 = max4(m0, m1);

        __shared__ float4 sm[8][CG];
        sm[pg][cg] = m0;
        __syncthreads();

        if (pg == 0) {
            #pragma unroll
            for (int g = 1; g < 8; ++g) m0 = max4(m0, sm[g][cg]);
            reinterpret_cast<float4*>(g_pooled)[(uint32_t)(((b * PH + ph) * PW + pw) * CG + cg)] = m0;
            // Publish: syncwarp orders lanes' STGs before lane 0's release RED.
            __syncwarp();
            if (cg == 0) {
                asm volatile("red.release.gpu.add.u32 [%0], %1;"
                             :: "l"(&g_ticket), "r"(1u) : "memory");
            }
        }
        return;
    }

    // ------------------------- COMBINE PATH -------------------------
    const int e  = blockIdx.y * 8 + blockIdx.x;   // 0..63
    const int wd = t >> 5;
    const int cg = t & 31;

    // Thread 0 acquire-spins until every pool block has published.
    if (t == 0) {
        unsigned int v;
        for (;;) {
            asm volatile("ld.acquire.gpu.u32 %0, [%1];"
                         : "=r"(v) : "l"(&g_ticket) : "memory");
            if (v >= (unsigned)NPOOL) break;
            __nanosleep(64);
        }
    }
    __syncthreads();   // broadcasts the acquire to all threads in the block

    for (int gw = e * 8 + wd; gw < NB * NS; gw += NEPI * 8) {
        const int b = gw / NS;
        const int s = gw - b * NS;
        const int cell = tab.base[s];
        const int n = tab.nmask[s];

        const float4* p = reinterpret_cast<const float4*>(g_pooled) +
                          (uint32_t)((b * PH * PW + cell) * CG + cg);

        // L2-coherent loads (L1 holds no stale pooled lines: pool never reads it)
        const float4 p00 = __ldcg(p);
        const float4 p01 = __ldcg(p + CG);
        const float4 p10 = __ldcg(p + PW * CG);
        const float4 p11 = __ldcg(p + (PW + 1) * CG);

        float4 acc = make_float4(0.f, 0.f, 0.f, 0.f);
        #pragma unroll 4
        for (int eIdx = 0; eIdx < n; ++eIdx) {
            const int mk = tab.mask[s][eIdx];
            const float w = tab.wgt[s][eIdx];
            float4 m = make_float4(-1e30f, -1e30f, -1e30f, -1e30f);
            if (mk & 1) m = max4(m, p00);
            if (mk & 2) m = max4(m, p01);
            if (mk & 4) m = max4(m, p10);
            if (mk & 8) m = max4(m, p11);
            acc.x += m.x * w; acc.y += m.y * w; acc.z += m.z * w; acc.w += m.w * w;
        }
        reinterpret_cast<float4*>(out)[(uint32_t)(gw * CG + cg)] = acc;
    }

    // Last combine block resets the tickets for the next graph replay.
    __syncthreads();
    if (t == 0) {
        unsigned int prev = atomicAdd(&g_done, 1u);
        if (prev == NEPI - 1) {
            g_done = 0;
            g_ticket = 0;
        }
    }
}

// ---------------------------------------------------------------------------
// Host-side MT19937 replicating numpy's legacy RandomState exactly.
// ---------------------------------------------------------------------------
namespace nprng {
struct MT { uint32_t mt[624]; int idx; };

static void mt_seed(MT& st, uint32_t s) {
    for (int i = 0; i < 624; ++i) {
        st.mt[i] = s;
        s = 1812433253u * (s ^ (s >> 30)) + (uint32_t)i + 1u;
    }
    st.idx = 624;
}

static uint32_t mt_next(MT& st) {
    if (st.idx >= 624) {
        for (int i = 0; i < 624; ++i) {
            uint32_t y = (st.mt[i] & 0x80000000u) | (st.mt[(i + 1) % 624] & 0x7fffffffu);
            st.mt[i] = st.mt[(i + 397) % 624] ^ (y >> 1) ^ ((y & 1u) ? 0x9908b0dfu : 0u);
        }
        st.idx = 0;
    }
    uint32_t y = st.mt[st.idx++];
    y ^= y >> 11;
    y ^= (y << 7)  & 0x9d2c5680u;
    y ^= (y << 15) & 0xefc60000u;
    y ^= y >> 18;
    return y;
}

// randint(0, 7): masked rejection, mask = 7
static int randint7(MT& st) {
    for (;;) {
        uint32_t v = mt_next(st) & 7u;
        if (v <= 6u) return (int)v;
    }
}
}  // namespace nprng

static void build_table(CornerTab& tab) {
    int ri[ITERS], ci[ITERS];
    for (int it = 0; it < ITERS; ++it) {
        nprng::MT st;
        nprng::mt_seed(st, 42u + (uint32_t)it);
        ri[it] = nprng::randint7(st);
        ci[it] = nprng::randint7(st);
    }
    memset(&tab, 0, sizeof(tab));
    for (int s = 0; s < NS; ++s) {
        const int oh = s / OW;
        const int ow = s - oh * OW;
        tab.base[s] = (unsigned char)(oh * PW + ow);

        int nM = 0;
        int masks[MAXM], counts[MAXM];
        for (int it = 0; it < ITERS; ++it) {
            const int i = ri[it], j = ci[it];
            int bitR = (oh < i) ? 1 : ((oh == i) ? 3 : 2);
            int bitC = (ow < j) ? 1 : ((ow == j) ? 3 : 2);
            int mk = 0;
            for (int r = 0; r < 2; ++r)
                for (int c = 0; c < 2; ++c)
                    if ((bitR >> r & 1) && (bitC >> c & 1)) mk |= 1 << (r * 2 + c);
            int found = -1;
            for (int e = 0; e < nM; ++e)
                if (masks[e] == mk) { found = e; break; }
            if (found >= 0) counts[found]++;
            else { masks[nM] = mk; counts[nM] = 1; nM++; }
        }
        tab.nmask[s] = (unsigned char)nM;
        for (int e = 0; e < nM; ++e) {
            tab.mask[s][e] = (unsigned char)masks[e];
            tab.wgt[s][e]  = (float)counts[e] / (float)ITERS;
        }
    }
}

extern "C" void kernel_launch(void* const* d_in, const int* in_sizes, int n_in,
                              void* d_out, int out_size) {
    (void)in_sizes; (void)n_in; (void)out_size;
    const float* x = (const float*)d_in[0];
    float* out = (float*)d_out;

    CornerTab tab;
    build_table(tab);

    // z = 0..NB-1: pool blocks (scheduled first, linear-bid order);
    // z = NB: 64 combine blocks (scheduled last, overlap the pool drain).
    dim3 grid(PW, PH, NB + 1);
    fused_kernel<<<grid, 256>>>(x, out, tab);
}

// round 16
// speedup vs baseline: 1.1008x; 1.1008x over previous
#include <cuda_runtime.h>
#include <cstdint>
#include <cstring>

// ---------------------------------------------------------------------------
// Problem constants
// ---------------------------------------------------------------------------
#define NB 32      // batch
#define IH 225
#define IW 225
#define C  128
#define PH 8       // pooled spatial (ceil(225/32))
#define PW 8
#define OH 7
#define OW 7
#define ITERS 10
#define CG 32      // float4 channel groups (C/4)
#define NS (OH * OW)   // 49 output spatial positions
#define MAXM 9     // max distinct corner-masks per position
#define ROWSTRIDE 7200u   // IW * CG, in float4 units (compile-time)

// 1 MB scratch for the pooled tensor [NB, PH, PW, C]
__device__ float g_pooled[NB * PH * PW * C];

__device__ __forceinline__ float4 max4(float4 a, float4 b) {
    a.x = fmaxf(a.x, b.x);
    a.y = fmaxf(a.y, b.y);
    a.z = fmaxf(a.z, b.z);
    a.w = fmaxf(a.w, b.w);
    return a;
}

// ---------------------------------------------------------------------------
// Kernel A: segmented 32x32 SAME max-pool. One block per (b, ph, pw) window.
// R12-measured hot loop (2-row unroll, 8 LDG.128 in flight, 32-bit offsets),
// with evict-first (__ldcs) streaming loads: input has zero reuse, keeps the
// pooled output lines resident in L2 for the combine kernel.
// ---------------------------------------------------------------------------
__global__ __launch_bounds__(256) void pool_kernel(const float* __restrict__ x) {
    const int pw = blockIdx.x;
    const int ph = blockIdx.y;
    const int b  = blockIdx.z;
    const int t  = threadIdx.x;
    const int cg = t & 31;    // float4 channel group 0..31
    const int pg = t >> 5;    // position group 0..7

    int h0 = ph * 32 - 15; if (h0 < 0) h0 = 0;
    int h1 = ph * 32 + 16; if (h1 > IH - 1) h1 = IH - 1;
    int w0 = pw * 32 - 15; if (w0 < 0) w0 = 0;
    int w1 = pw * 32 + 16; if (w1 > IW - 1) w1 = IW - 1;
    const int nw = w1 - w0 + 1;

    // Base float4 pointer for this (b, w0, cg); all further offsets 32-bit.
    const float4* __restrict__ xb =
        reinterpret_cast<const float4*>(x) +
        (uint32_t)b * (uint32_t)(IH * IW * CG) + (uint32_t)(w0 * CG + cg);

    float4 m0 = make_float4(-1e30f, -1e30f, -1e30f, -1e30f);
    float4 m1 = m0;

    if (nw == 32) {
        int h = h0;
        for (; h + 1 <= h1; h += 2) {
            const uint32_t o0 = (uint32_t)h * ROWSTRIDE;
            const uint32_t o1 = o0 + ROWSTRIDE;
            #pragma unroll
            for (int k = 0; k < 4; ++k) {
                const uint32_t off = (uint32_t)(pg + 8 * k) * (uint32_t)CG;
                m0 = max4(m0, __ldcs(xb + o0 + off));
                m1 = max4(m1, __ldcs(xb + o1 + off));
            }
        }
        if (h <= h1) {
            const uint32_t o0 = (uint32_t)h * ROWSTRIDE;
            #pragma unroll
            for (int k = 0; k < 4; ++k)
                m0 = max4(m0, __ldcs(xb + o0 + (uint32_t)(pg + 8 * k) * (uint32_t)CG));
        }
    } else {
        int h = h0;
        for (; h + 1 <= h1; h += 2) {
            const uint32_t o0 = (uint32_t)h * ROWSTRIDE;
            const uint32_t o1 = o0 + ROWSTRIDE;
            #pragma unroll
            for (int k = 0; k < 5; ++k) {
                const int w = pg + 8 * k;
                if (w < nw) {
                    const uint32_t off = (uint32_t)w * (uint32_t)CG;
                    m0 = max4(m0, __ldcs(xb + o0 + off));
                    m1 = max4(m1, __ldcs(xb + o1 + off));
                }
            }
        }
        if (h <= h1) {
            const uint32_t o0 = (uint32_t)h * ROWSTRIDE;
            #pragma unroll
            for (int k = 0; k < 5; ++k) {
                const int w = pg + 8 * k;
                if (w < nw) m0 = max4(m0, __ldcs(xb + o0 + (uint32_t)w * (uint32_t)CG));
            }
        }
    }
    m0 = max4(m0, m1);

    __shared__ float4 sm[8][CG];
    sm[pg][cg] = m0;
    __syncthreads();

    if (pg == 0) {
        #pragma unroll
        for (int g = 1; g < 8; ++g) m0 = max4(m0, sm[g][cg]);
        reinterpret_cast<float4*>(g_pooled)[(uint32_t)(((b * PH + ph) * PW + pw) * CG + cg)] = m0;
    }

    // PDL: allow the dependent (combine) grid to begin launching.
    asm volatile("griddepcontrol.launch_dependents;" ::: "memory");
}

// ---------------------------------------------------------------------------
// Kernel B: corner-mask combine (4 loads + register-only selection).
// PDL consumer: waits for the pool grid's memory before reading g_pooled.
// ---------------------------------------------------------------------------
struct CornerTab {
    unsigned char base[NS];            // corner cell id (oh*PW + ow)
    unsigned char nmask[NS];           // number of distinct masks
    unsigned char mask[NS][MAXM];      // bit0=c00 bit1=c01 bit2=c10 bit3=c11
    float         wgt[NS][MAXM];       // multiplicity / ITERS
};

__global__ __launch_bounds__(256) void combine_kernel(float* __restrict__ out, CornerTab tab) {
    const int gw = blockIdx.x * 8 + (threadIdx.x >> 5);   // warp = (b, s)
    const int cg = threadIdx.x & 31;
    const int b  = gw / NS;
    const int s  = gw - b * NS;

    bool active = (gw < NB * NS);
    int cell = 0, n = 0;
    if (active) {
        cell = tab.base[s];
        n = tab.nmask[s];
    }

    asm volatile("griddepcontrol.wait;" ::: "memory");
    if (!active) return;

    const float4* p = reinterpret_cast<const float4*>(g_pooled) +
                      (uint32_t)((b * PH * PW + cell) * CG + cg);

    const float4 p00 = __ldg(p);
    const float4 p01 = __ldg(p + CG);
    const float4 p10 = __ldg(p + PW * CG);
    const float4 p11 = __ldg(p + (PW + 1) * CG);

    float4 acc = make_float4(0.f, 0.f, 0.f, 0.f);
    #pragma unroll 4
    for (int e = 0; e < n; ++e) {
        const int mk = tab.mask[s][e];
        const float w = tab.wgt[s][e];
        float4 m = make_float4(-1e30f, -1e30f, -1e30f, -1e30f);
        if (mk & 1) m = max4(m, p00);
        if (mk & 2) m = max4(m, p01);
        if (mk & 4) m = max4(m, p10);
        if (mk & 8) m = max4(m, p11);
        acc.x += m.x * w; acc.y += m.y * w; acc.z += m.z * w; acc.w += m.w * w;
    }
    reinterpret_cast<float4*>(out)[(uint32_t)(gw * CG + cg)] = acc;
}

// ---------------------------------------------------------------------------
// Host-side MT19937 replicating numpy's legacy RandomState exactly.
// ---------------------------------------------------------------------------
namespace nprng {
struct MT { uint32_t mt[624]; int idx; };

static void mt_seed(MT& st, uint32_t s) {
    for (int i = 0; i < 624; ++i) {
        st.mt[i] = s;
        s = 1812433253u * (s ^ (s >> 30)) + (uint32_t)i + 1u;
    }
    st.idx = 624;
}

static uint32_t mt_next(MT& st) {
    if (st.idx >= 624) {
        for (int i = 0; i < 624; ++i) {
            uint32_t y = (st.mt[i] & 0x80000000u) | (st.mt[(i + 1) % 624] & 0x7fffffffu);
            st.mt[i] = st.mt[(i + 397) % 624] ^ (y >> 1) ^ ((y & 1u) ? 0x9908b0dfu : 0u);
        }
        st.idx = 0;
    }
    uint32_t y = st.mt[st.idx++];
    y ^= y >> 11;
    y ^= (y << 7)  & 0x9d2c5680u;
    y ^= (y << 15) & 0xefc60000u;
    y ^= y >> 18;
    return y;
}

// randint(0, 7): masked rejection, mask = 7
static int randint7(MT& st) {
    for (;;) {
        uint32_t v = mt_next(st) & 7u;
        if (v <= 6u) return (int)v;
    }
}
}  // namespace nprng

static void build_table(CornerTab& tab) {
    int ri[ITERS], ci[ITERS];
    for (int it = 0; it < ITERS; ++it) {
        nprng::MT st;
        nprng::mt_seed(st, 42u + (uint32_t)it);
        ri[it] = nprng::randint7(st);
        ci[it] = nprng::randint7(st);
    }
    memset(&tab, 0, sizeof(tab));
    for (int s = 0; s < NS; ++s) {
        const int oh = s / OW;
        const int ow = s - oh * OW;
        tab.base[s] = (unsigned char)(oh * PW + ow);

        int nM = 0;
        int masks[MAXM], counts[MAXM];
        for (int it = 0; it < ITERS; ++it) {
            const int i = ri[it], j = ci[it];
            int bitR = (oh < i) ? 1 : ((oh == i) ? 3 : 2);
            int bitC = (ow < j) ? 1 : ((ow == j) ? 3 : 2);
            int mk = 0;
            for (int r = 0; r < 2; ++r)
                for (int c = 0; c < 2; ++c)
                    if ((bitR >> r & 1) && (bitC >> c & 1)) mk |= 1 << (r * 2 + c);
            int found = -1;
            for (int e = 0; e < nM; ++e)
                if (masks[e] == mk) { found = e; break; }
            if (found >= 0) counts[found]++;
            else { masks[nM] = mk; counts[nM] = 1; nM++; }
        }
        tab.nmask[s] = (unsigned char)nM;
        for (int e = 0; e < nM; ++e) {
            tab.mask[s][e] = (unsigned char)masks[e];
            tab.wgt[s][e]  = (float)counts[e] / (float)ITERS;
        }
    }
}

extern "C" void kernel_launch(void* const* d_in, const int* in_sizes, int n_in,
                              void* d_out, int out_size) {
    (void)in_sizes; (void)n_in; (void)out_size;
    const float* x = (const float*)d_in[0];
    float* out = (float*)d_out;

    CornerTab tab;
    build_table(tab);

    dim3 gridA(PW, PH, NB);
    pool_kernel<<<gridA, 256>>>(x);

    const int nwarps = NB * NS;                 // 1568 warps
    cudaLaunchConfig_t cfg = {};
    cfg.gridDim  = dim3((nwarps + 7) / 8, 1, 1);
    cfg.blockDim = dim3(256, 1, 1);
    cfg.dynamicSmemBytes = 0;
    cfg.stream = 0;
    cudaLaunchAttribute attrs[1];
    attrs[0].id = cudaLaunchAttributeProgrammaticStreamSerialization;
    attrs[0].val.programmaticStreamSerializationAllowed = 1;
    cfg.attrs = attrs;
    cfg.numAttrs = 1;
    cudaLaunchKernelEx(&cfg, combine_kernel, out, tab);
}